// round 16
// baseline (speedup 1.0000x reference)
#include <cuda_runtime.h>
#include <cuda_bf16.h>
#include <cstdint>
#include <math.h>

#define H_DIM 4096
#define E_DIM 64
#define GRID 296
#define THREADS 448
#define TILE 96
#define FF_BASE 28416
#define FF_PER 15
#define KCHUNK 32
#define NCHUNKS 128
#define GAP_THRESH 5e-4f
#define CPAD 68

#define OFF_AHI 0
#define OFF_ALO 6144
#define OFF_BHI 12288
#define OFF_BLO 16384
#define OFF_FFA 20480
#define STAGE 22528
#define SMEM_BYTES 45056
#define SWZ(r, c) ((uint32_t)((r) * 64 + ((((c) ^ (((r) >> 1) & 3))) << 4)))

__device__ __forceinline__ uint32_t smem_to_u32(const void* p) {
    uint32_t a;
    asm("{ .reg .u64 t; cvta.to.shared.u64 t, %1; cvt.u32.u64 %0, t; }" : "=r"(a) : "l"(p));
    return a;
}
#define LDSM_X4(r0, r1, r2, r3, addr)                                          \
    asm volatile("ldmatrix.sync.aligned.m8n8.x4.shared.b16 {%0,%1,%2,%3}, [%4];" \
                 : "=r"(r0), "=r"(r1), "=r"(r2), "=r"(r3) : "r"(addr))
__device__ __forceinline__ void mma_bf16(float* c, const uint32_t* a,
                                         uint32_t b0, uint32_t b1) {
    asm volatile(
        "mma.sync.aligned.m16n8k16.row.col.f32.bf16.bf16.f32 "
        "{%0,%1,%2,%3}, {%4,%5,%6,%7}, {%8,%9}, {%0,%1,%2,%3};"
        : "+f"(c[0]), "+f"(c[1]), "+f"(c[2]), "+f"(c[3])
        : "r"(a[0]), "r"(a[1]), "r"(a[2]), "r"(a[3]), "r"(b0), "r"(b1));
}
__device__ __forceinline__ uint32_t bf2(float a, float b) {
    __nv_bfloat162 t = __floats2bfloat162_rn(a, b);
    return *(uint32_t*)&t;
}
__device__ __forceinline__ void split8(const float4 p0, const float4 p1,
                                       uint4& hi, uint4& lo) {
    hi.x = bf2(p0.x, p0.y); hi.y = bf2(p0.z, p0.w);
    hi.z = bf2(p1.x, p1.y); hi.w = bf2(p1.z, p1.w);
    float hx = __uint_as_float(hi.x << 16), hy = __uint_as_float(hi.x & 0xffff0000u);
    float hz = __uint_as_float(hi.y << 16), hw = __uint_as_float(hi.y & 0xffff0000u);
    lo.x = bf2(p0.x - hx, p0.y - hy); lo.y = bf2(p0.z - hz, p0.w - hw);
    hx = __uint_as_float(hi.z << 16); hy = __uint_as_float(hi.z & 0xffff0000u);
    hz = __uint_as_float(hi.w << 16); hw = __uint_as_float(hi.w & 0xffff0000u);
    lo.z = bf2(p1.x - hx, p1.y - hy); lo.w = bf2(p1.z - hz, p1.w - hw);
}

__device__ __nv_bfloat16 g_Whi[E_DIM * H_DIM];
__device__ __nv_bfloat16 g_Wlo[E_DIM * H_DIM];
__device__ int g_flag_count;
__device__ int g_flag_tokens[32768];

__global__ __launch_bounds__(256) void w_split(const float* __restrict__ W) {
    if (blockIdx.x == 0 && threadIdx.x == 0) g_flag_count = 0;
    for (int i = blockIdx.x * 256 + threadIdx.x; i < E_DIM * H_DIM; i += 256 * 256) {
        float w = W[i];
        __nv_bfloat16 hi = __float2bfloat16_rn(w);
        g_Whi[i] = hi;
        g_Wlo[i] = __float2bfloat16_rn(w - __bfloat162float(hi));
    }
}

// per-token warp softmax/top2/flag (all lanes call; wr gates stores)
__device__ __forceinline__ void tok_epi(float v0, float v1, long gtok, int lane,
                                        float* C, float* P, float* IDX, bool wr) {
    if (wr) { C[gtok * 64 + lane] = v0; C[gtok * 64 + lane + 32] = v1; }
    float m = fmaxf(v0, v1);
#pragma unroll
    for (int o = 16; o; o >>= 1) m = fmaxf(m, __shfl_xor_sync(0xffffffffu, m, o));
    float e0 = __expf(v0 - m), e1 = __expf(v1 - m);
    float s = e0 + e1;
#pragma unroll
    for (int o = 16; o; o >>= 1) s += __shfl_xor_sync(0xffffffffu, s, o);
    float inv = 1.0f / s;
    if (wr) { P[gtok * 64 + lane] = e0 * inv; P[gtok * 64 + lane + 32] = e1 * inv; }
    float bv; int bi;
    if (v0 >= v1) { bv = v0; bi = lane; } else { bv = v1; bi = lane + 32; }
#pragma unroll
    for (int o = 16; o; o >>= 1) {
        float ov = __shfl_xor_sync(0xffffffffu, bv, o);
        int oi = __shfl_xor_sync(0xffffffffu, bi, o);
        if (ov > bv || (ov == bv && oi < bi)) { bv = ov; bi = oi; }
    }
    float c0 = (lane == bi) ? -INFINITY : v0;
    float c1 = (lane + 32 == bi) ? -INFINITY : v1;
    float sv; int si;
    if (c0 >= c1) { sv = c0; si = lane; } else { sv = c1; si = lane + 32; }
#pragma unroll
    for (int o = 16; o; o >>= 1) {
        float ov = __shfl_xor_sync(0xffffffffu, sv, o);
        int oi = __shfl_xor_sync(0xffffffffu, si, o);
        if (ov > sv || (ov == sv && oi < si)) { sv = ov; si = oi; }
    }
    float d0 = (lane == bi || lane == si) ? -INFINITY : v0;
    float d1 = (lane + 32 == bi || lane + 32 == si) ? -INFINITY : v1;
    float tv = fmaxf(d0, d1);
#pragma unroll
    for (int o = 16; o; o >>= 1) tv = fmaxf(tv, __shfl_xor_sync(0xffffffffu, tv, o));
    if (lane == 0 && wr) {
        IDX[gtok * 2 + 0] = (float)bi;
        IDX[gtok * 2 + 1] = (float)si;
        if ((bv - sv) < GAP_THRESH || (sv - tv) < GAP_THRESH) {
            int slot = atomicAdd(&g_flag_count, 1);
            if (slot < 32768) g_flag_tokens[slot] = (int)gtok;
        }
    }
}

__global__ __launch_bounds__(THREADS, 1) void router_hybrid(const float* __restrict__ A,
                                                            const float* __restrict__ W,
                                                            float* __restrict__ C,
                                                            float* __restrict__ P,
                                                            float* __restrict__ IDX) {
    __shared__ __align__(16) char smem[SMEM_BYTES];
    const uint32_t sb = smem_to_u32(smem);
    float* Cs = (float*)smem;

    const int tid = threadIdx.x;
    const int wid = tid >> 5;
    const int lane = tid & 31;
    const long tokenBase = (long)blockIdx.x * TILE;
    const int ffbase = FF_BASE + blockIdx.x * FF_PER;

    if (wid < 12) {
        // ================= HMMA path (96 tokens x 64 experts, bf16 3-pass) ====
        float acc[4][4];
#pragma unroll
        for (int j = 0; j < 4; j++)
#pragma unroll
            for (int i = 0; i < 4; i++) acc[j][i] = 0.0f;

        const int lrow = tid >> 2, lc = tid & 3;  // A loader: 384 thr, 96 rows
        const float* aP = A + (tokenBase + lrow) * H_DIM + lc * 8;
        const uint32_t sA = SWZ(lrow, lc);

        const int rg = wid >> 1, E0 = (wid & 1) * 32;
        const int arow = rg * 16 + (lane & 15);
        const uint32_t axr = (uint32_t)((arow >> 1) & 3);
        const uint32_t ahalf = (uint32_t)((lane >> 4) & 1);
        const int ebase = (lane & 7) + ((lane >> 4) & 1) * 8;
        const uint32_t bhalf = (uint32_t)((lane >> 3) & 1);

        // prologue chunk 0
        {
            float4 p0 = *(const float4*)(aP), p1 = *(const float4*)(aP + 4);
            uint4 h, l;
            split8(p0, p1, h, l);
            *(uint4*)(smem + OFF_AHI + sA) = h;
            *(uint4*)(smem + OFF_ALO + sA) = l;
        }
        __syncthreads();

        for (int chunk = 0; chunk < NCHUNKS; chunk++) {
            const uint32_t cb = (uint32_t)((chunk & 1) * STAGE);
            const uint32_t nb = (uint32_t)(((chunk + 1) & 1) * STAGE);
            const bool more = (chunk + 1 < NCHUNKS);
            float4 p0, p1;
            if (more) {
                const int kb = (chunk + 1) * KCHUNK;
                p0 = *(const float4*)(aP + kb);
                p1 = *(const float4*)(aP + kb + 4);
            }
#pragma unroll
            for (int s = 0; s < 2; s++) {
                uint32_t ah[4], al[4];
                {
                    const uint32_t ach = (uint32_t)(2 * s) + ahalf;
                    const uint32_t ao = (uint32_t)(arow * 64) + ((ach ^ axr) << 4);
                    LDSM_X4(ah[0], ah[1], ah[2], ah[3], sb + cb + OFF_AHI + ao);
                    LDSM_X4(al[0], al[1], al[2], al[3], sb + cb + OFF_ALO + ao);
                }
                uint32_t bh[8], bl[8];
#pragma unroll
                for (int jt = 0; jt < 2; jt++) {
                    const int erow = E0 + jt * 16 + ebase;
                    const uint32_t bch = (uint32_t)(2 * s) + bhalf;
                    const uint32_t bo = (uint32_t)(erow * 64) +
                                        ((bch ^ (uint32_t)((erow >> 1) & 3)) << 4);
                    LDSM_X4(bh[4 * jt], bh[4 * jt + 1], bh[4 * jt + 2], bh[4 * jt + 3],
                            sb + cb + OFF_BHI + bo);
                    LDSM_X4(bl[4 * jt], bl[4 * jt + 1], bl[4 * jt + 2], bl[4 * jt + 3],
                            sb + cb + OFF_BLO + bo);
                }
#pragma unroll
                for (int jt = 0; jt < 2; jt++) {
                    mma_bf16(acc[2 * jt], ah, bh[4 * jt], bh[4 * jt + 1]);
                    mma_bf16(acc[2 * jt + 1], ah, bh[4 * jt + 2], bh[4 * jt + 3]);
                }
#pragma unroll
                for (int jt = 0; jt < 2; jt++) {
                    mma_bf16(acc[2 * jt], ah, bl[4 * jt], bl[4 * jt + 1]);
                    mma_bf16(acc[2 * jt + 1], ah, bl[4 * jt + 2], bl[4 * jt + 3]);
                }
#pragma unroll
                for (int jt = 0; jt < 2; jt++) {
                    mma_bf16(acc[2 * jt], al, bh[4 * jt], bh[4 * jt + 1]);
                    mma_bf16(acc[2 * jt + 1], al, bh[4 * jt + 2], bh[4 * jt + 3]);
                }
            }
            if (more) {
                uint4 h, l;
                split8(p0, p1, h, l);
                *(uint4*)(smem + nb + OFF_AHI + sA) = h;
                *(uint4*)(smem + nb + OFF_ALO + sA) = l;
            }
            __syncthreads();
        }

        // epilogue: stage Cs then per-warp softmax for 8 tokens
        {
            const int r0 = rg * 16 + (lane >> 2);
            const int cbo = E0 + 2 * (lane & 3);
#pragma unroll
            for (int nt = 0; nt < 4; nt++) {
                const int col = cbo + nt * 8;
                *(float2*)(Cs + r0 * CPAD + col) = make_float2(acc[nt][0], acc[nt][1]);
                *(float2*)(Cs + (r0 + 8) * CPAD + col) = make_float2(acc[nt][2], acc[nt][3]);
            }
        }
        __syncthreads();
#pragma unroll 1
        for (int i = 0; i < 8; i++) {
            const int tok = wid * 8 + i;
            tok_epi(Cs[tok * CPAD + lane], Cs[tok * CPAD + lane + 32],
                    tokenBase + tok, lane, C, P, IDX, true);
        }
    } else {
        // ============ FF path: B loader + FFA stage + fp32 tokens =============
        const int ft = tid - 384;  // 0..63
        const __nv_bfloat16* bhP = g_Whi + (long)ft * H_DIM;
        const __nv_bfloat16* blP = g_Wlo + (long)ft * H_DIM;
        const int frow = ft >> 2, fcol = ft & 3;            // FFA: row 0..15
        const int ftok = ffbase + frow;
        const bool fok = (frow < FF_PER) && (ftok < 32768);
        const float* aFF = A + (long)ftok * H_DIM + fcol * 8;
        const float* wq0 = W + (long)lane * H_DIM;
        const float* wq1 = W + (long)(lane + 32) * H_DIM;
        const int jb = (wid - 12) * 8;                      // my token window
        const int cnt = (wid == 12) ? 8 : 7;

        float fa[8], fb[8];
#pragma unroll
        for (int i = 0; i < 8; i++) { fa[i] = 0.0f; fb[i] = 0.0f; }

        // prologue chunk 0
        {
#pragma unroll
            for (int c = 0; c < 4; c++) {
                *(uint4*)(smem + OFF_BHI + SWZ(ft, c)) = *(const uint4*)(bhP + c * 8);
                *(uint4*)(smem + OFF_BLO + SWZ(ft, c)) = *(const uint4*)(blP + c * 8);
            }
            if (fok) {
                *(float4*)(smem + OFF_FFA + frow * 128 + fcol * 32) = *(const float4*)(aFF);
                *(float4*)(smem + OFF_FFA + frow * 128 + fcol * 32 + 16) = *(const float4*)(aFF + 4);
            }
        }
        __syncthreads();

        for (int chunk = 0; chunk < NCHUNKS; chunk++) {
            const uint32_t cb = (uint32_t)((chunk & 1) * STAGE);
            const uint32_t nb = (uint32_t)(((chunk + 1) & 1) * STAGE);
            const bool more = (chunk + 1 < NCHUNKS);
            const int kb = chunk * KCHUNK;
            uint4 ph[4], pl[4];
            float4 pf0, pf1;
            if (more) {
                const int nk = kb + KCHUNK;
#pragma unroll
                for (int c = 0; c < 4; c++) {
                    ph[c] = *(const uint4*)(bhP + nk + c * 8);
                    pl[c] = *(const uint4*)(blP + nk + c * 8);
                }
                if (fok) { pf0 = *(const float4*)(aFF + nk); pf1 = *(const float4*)(aFF + nk + 4); }
            }
            // FF compute on current chunk
            const char* ffa = smem + cb + OFF_FFA;
#pragma unroll
            for (int q = 0; q < 8; q++) {
                float4 w0 = *(const float4*)(wq0 + kb + q * 4);
                float4 w1 = *(const float4*)(wq1 + kb + q * 4);
#pragma unroll
                for (int i = 0; i < 8; i++) {
                    float4 a4 = *(const float4*)(ffa + (jb + i) * 128 + q * 16);
                    fa[i] = __fmaf_rn(a4.x, w0.x, fa[i]);
                    fa[i] = __fmaf_rn(a4.y, w0.y, fa[i]);
                    fa[i] = __fmaf_rn(a4.z, w0.z, fa[i]);
                    fa[i] = __fmaf_rn(a4.w, w0.w, fa[i]);
                    fb[i] = __fmaf_rn(a4.x, w1.x, fb[i]);
                    fb[i] = __fmaf_rn(a4.y, w1.y, fb[i]);
                    fb[i] = __fmaf_rn(a4.z, w1.z, fb[i]);
                    fb[i] = __fmaf_rn(a4.w, w1.w, fb[i]);
                }
            }
            if (more) {
#pragma unroll
                for (int c = 0; c < 4; c++) {
                    *(uint4*)(smem + nb + OFF_BHI + SWZ(ft, c)) = ph[c];
                    *(uint4*)(smem + nb + OFF_BLO + SWZ(ft, c)) = pl[c];
                }
                if (fok) {
                    *(float4*)(smem + nb + OFF_FFA + frow * 128 + fcol * 32) = pf0;
                    *(float4*)(smem + nb + OFF_FFA + frow * 128 + fcol * 32 + 16) = pf1;
                }
            }
            __syncthreads();
        }

        // FF epilogue: own tokens from registers (no smem)
#pragma unroll 1
        for (int i = 0; i < 8; i++) {
            const long gtok = ffbase + jb + i;
            const bool wr = (i < cnt) && (gtok < 32768);
            tok_epi(fa[i], fb[i], gtok, lane, C, P, IDX, wr);
        }
        __syncthreads();  // matches MMA path's Cs barrier
    }
}

// two-tier fp64-free refine (validated R13 body)
__global__ __launch_bounds__(256) void refine_ties(const float* __restrict__ A,
                                                   const float* __restrict__ W,
                                                   float* __restrict__ IDX) {
    __shared__ float sA[H_DIM];
    __shared__ double dpart[E_DIM][4];
    __shared__ double dsum[2];
    __shared__ float fmx[2];
    __shared__ float af_s[E_DIM];
    __shared__ int s_need;

    int n = g_flag_count;
    if (n > 32768) n = 32768;
    const int t = threadIdx.x, e = t & 63, seg = t >> 6;

    for (int it = blockIdx.x; it < n; it += gridDim.x) {
        const int tok = g_flag_tokens[it];
        const float* arow = A + (long)tok * H_DIM;
        for (int k = t * 4; k < H_DIM; k += 1024)
            *(float4*)(sA + k) = *(const float4*)(arow + k);
        __syncthreads();

        const float* wrow = W + (long)e * H_DIM + seg * 1024;
        const float* aseg = sA + seg * 1024;
        {
            float a0 = 0, a1 = 0, a2 = 0, a3 = 0;
#pragma unroll 4
            for (int k = 0; k < 1024; k += 4) {
                float4 w4 = *(const float4*)(wrow + k);
                float4 a4 = *(const float4*)(aseg + k);
                a0 = __fmaf_rn(a4.x, w4.x, a0);
                a1 = __fmaf_rn(a4.y, w4.y, a1);
                a2 = __fmaf_rn(a4.z, w4.z, a2);
                a3 = __fmaf_rn(a4.w, w4.w, a3);
            }
            dpart[e][seg] = ((double)a0 + (double)a1) + ((double)a2 + (double)a3);
        }
        __syncthreads();

        for (int tier = 0; tier < 2; tier++) {
            double dl = 0.0, ex = 0.0;
            if (t < 64) {
                dl = (dpart[e][0] + dpart[e][1]) + (dpart[e][2] + dpart[e][3]);
                float mv = (float)dl;
#pragma unroll
                for (int o = 16; o; o >>= 1)
                    mv = fmaxf(mv, __shfl_xor_sync(0xffffffffu, mv, o));
                if ((t & 31) == 0) fmx[t >> 5] = mv;
            }
            __syncthreads();
            if (t < 64) {
                const float m = fmaxf(fmx[0], fmx[1]);
                ex = exp(dl - (double)m);
                double sm = ex;
#pragma unroll
                for (int o = 16; o; o >>= 1)
                    sm += __shfl_xor_sync(0xffffffffu, sm, o);
                if ((t & 31) == 0) dsum[t >> 5] = sm;
            }
            __syncthreads();
            if (t < 64) af_s[e] = (float)(ex / (dsum[0] + dsum[1]));
            __syncthreads();

            if (t == 0) {
                int bi = 0;
#pragma unroll
                for (int i = 1; i < E_DIM; i++)
                    if (af_s[i] > af_s[bi]) bi = i;
                int si = (bi == 0) ? 1 : 0;
#pragma unroll
                for (int i = 0; i < E_DIM; i++) {
                    if (i == bi || i == si) continue;
                    if (af_s[i] > af_s[si]) si = i;
                }
                float ti = -INFINITY;
#pragma unroll
                for (int i = 0; i < E_DIM; i++) {
                    if (i == bi || i == si) continue;
                    ti = fmaxf(ti, af_s[i]);
                }
                const int ambiguous = (tier == 0) &&
                    ((af_s[bi] - af_s[si] < 1e-5f) || (af_s[si] - ti < 1e-5f));
                s_need = ambiguous;
                if (!ambiguous) {
                    IDX[(long)tok * 2 + 0] = (float)bi;
                    IDX[(long)tok * 2 + 1] = (float)si;
                }
            }
            __syncthreads();
            if (!s_need) break;
            {
                float s = 0.0f, c = 0.0f, ce = 0.0f;
#pragma unroll 4
                for (int k = 0; k < 1024; k += 4) {
                    float4 w4 = *(const float4*)(wrow + k);
                    float4 a4 = *(const float4*)(aseg + k);
#define ACC1(av, wv) {                                   \
                    float p = __fmul_rn((av), (wv));     \
                    ce += __fmaf_rn((av), (wv), -p);     \
                    float t2 = __fadd_rn(s, p);          \
                    float z = t2 - s;                    \
                    c += (s - (t2 - z)) + (p - z);       \
                    s = t2; }
                    ACC1(a4.x, w4.x); ACC1(a4.y, w4.y);
                    ACC1(a4.z, w4.z); ACC1(a4.w, w4.w);
#undef ACC1
                }
                dpart[e][seg] = (double)s + ((double)c + (double)ce);
            }
            __syncthreads();
        }
        __syncthreads();
    }
}

extern "C" void kernel_launch(void* const* d_in, const int* in_sizes, int n_in,
                              void* d_out, int out_size) {
    const float* A = (const float*)d_in[0];
    const float* W = (const float*)d_in[1];
    const int T = in_sizes[0] / H_DIM;  // 32768

    float* out = (float*)d_out;
    float* logits = out;
    float* affin = out + (long)T * E_DIM;
    float* idx = out + 2L * T * E_DIM;

    w_split<<<256, 256>>>(W);
    router_hybrid<<<GRID, THREADS>>>(A, W, logits, affin, idx);
    refine_ties<<<256, 256>>>(A, W, idx);
}

// round 17
// speedup vs baseline: 2.9954x; 2.9954x over previous
#include <cuda_runtime.h>
#include <cuda_bf16.h>
#include <cstdint>
#include <math.h>

#define H_DIM 4096
#define E_DIM 64
#define TILE_M 128
#define KCHUNK 32
#define NCHUNKS (H_DIM / KCHUNK)   // 128
#define GAP_THRESH 5e-4f
#define CPAD 68

// stage layout (bytes), SW64-swizzled tight tiles (64 B rows)
#define OFF_AHI 0
#define OFF_ALO 8192
#define OFF_BHI 16384
#define OFF_BLO 20480
#define STAGE_BYTES 24576
#define SMEM_BYTES 49152          // 2 stages; epilogue C-stage overlays

#define SWZ(r, c) ((uint32_t)((r) * 64 + ((((c) ^ (((r) >> 1) & 3))) << 4)))

__device__ __forceinline__ uint32_t smem_to_u32(const void* p) {
    uint32_t a;
    asm("{ .reg .u64 t; cvta.to.shared.u64 t, %1; cvt.u32.u64 %0, t; }" : "=r"(a) : "l"(p));
    return a;
}

#define LDSM_X4(r0, r1, r2, r3, addr)                                          \
    asm volatile("ldmatrix.sync.aligned.m8n8.x4.shared.b16 {%0,%1,%2,%3}, [%4];" \
                 : "=r"(r0), "=r"(r1), "=r"(r2), "=r"(r3) : "r"(addr))

__device__ __forceinline__ void mma_bf16(float* c, const uint32_t* a,
                                         uint32_t b0, uint32_t b1) {
    asm volatile(
        "mma.sync.aligned.m16n8k16.row.col.f32.bf16.bf16.f32 "
        "{%0,%1,%2,%3}, {%4,%5,%6,%7}, {%8,%9}, {%0,%1,%2,%3};"
        : "+f"(c[0]), "+f"(c[1]), "+f"(c[2]), "+f"(c[3])
        : "r"(a[0]), "r"(a[1]), "r"(a[2]), "r"(a[3]), "r"(b0), "r"(b1));
}

__device__ __forceinline__ uint32_t bf2(float a, float b) {
    __nv_bfloat162 t = __floats2bfloat162_rn(a, b);
    return *(uint32_t*)&t;
}

// split 8 fp32 -> 16B bf16 hi + 16B bf16 lo
__device__ __forceinline__ void split8(const float4 p0, const float4 p1,
                                       uint4& hi, uint4& lo) {
    hi.x = bf2(p0.x, p0.y); hi.y = bf2(p0.z, p0.w);
    hi.z = bf2(p1.x, p1.y); hi.w = bf2(p1.z, p1.w);
    float hx = __uint_as_float(hi.x << 16), hy = __uint_as_float(hi.x & 0xffff0000u);
    float hz = __uint_as_float(hi.y << 16), hw = __uint_as_float(hi.y & 0xffff0000u);
    lo.x = bf2(p0.x - hx, p0.y - hy); lo.y = bf2(p0.z - hz, p0.w - hw);
    hx = __uint_as_float(hi.z << 16); hy = __uint_as_float(hi.z & 0xffff0000u);
    hz = __uint_as_float(hi.w << 16); hw = __uint_as_float(hi.w & 0xffff0000u);
    lo.z = bf2(p1.x - hx, p1.y - hy); lo.w = bf2(p1.z - hz, p1.w - hw);
}

// ---------------------------------------------------------------------------
// Globals: pre-split W (bf16 hi/lo) + near-tie flag list
// ---------------------------------------------------------------------------
__device__ __nv_bfloat16 g_Whi[E_DIM * H_DIM];
__device__ __nv_bfloat16 g_Wlo[E_DIM * H_DIM];
__device__ int g_flag_count;
__device__ int g_flag_tokens[32768];

__global__ __launch_bounds__(256) void w_split(const float* __restrict__ W) {
    if (blockIdx.x == 0 && threadIdx.x == 0) g_flag_count = 0;
    for (int i = blockIdx.x * 256 + threadIdx.x; i < E_DIM * H_DIM; i += 256 * 256) {
        float w = W[i];
        __nv_bfloat16 hi = __float2bfloat16_rn(w);
        g_Whi[i] = hi;
        g_Wlo[i] = __float2bfloat16_rn(w - __bfloat162float(hi));
    }
}

// ---------------------------------------------------------------------------
// HMMA GEMM (bf16 hi/lo, 3 passes), double-buffered + fused epilogue.
// (champion round-10 GEMM, verbatim)
// ---------------------------------------------------------------------------
__global__ __launch_bounds__(256, 2) void router_gemm_mma(const float* __restrict__ A,
                                                          float* __restrict__ C,
                                                          float* __restrict__ P,
                                                          float* __restrict__ IDX) {
    __shared__ __align__(16) char smem[SMEM_BYTES];
    const uint32_t sb = smem_to_u32(smem);
    float* Cs = (float*)smem;

    const int tid = threadIdx.x;
    const int wid = tid >> 5;
    const int lane = tid & 31;
    const long tokenBase = (long)blockIdx.x * TILE_M;

    float acc[8][4];
#pragma unroll
    for (int j = 0; j < 8; j++)
#pragma unroll
        for (int i = 0; i < 4; i++) acc[j][i] = 0.0f;

    const int lrow = tid >> 2;           // 0..63
    const int lc = tid & 3;              // chunk
    const int lel = lc * 8;              // elem offset
    const float* aP0 = A + (tokenBase + lrow) * H_DIM + lel;
    const float* aP1 = A + (tokenBase + lrow + 64) * H_DIM + lel;
    const __nv_bfloat16* whP = g_Whi + (long)lrow * H_DIM + lel;
    const __nv_bfloat16* wlP = g_Wlo + (long)lrow * H_DIM + lel;
    const uint32_t sA0 = SWZ(lrow, lc), sA1 = SWZ(lrow + 64, lc), sB = SWZ(lrow, lc);

    const int arow = wid * 16 + (lane & 15);
    const uint32_t axr = (uint32_t)((arow >> 1) & 3);
    const uint32_t ahalf = (uint32_t)((lane >> 4) & 1);
    const int ebase = (lane & 7) + ((lane >> 4) & 1) * 8;
    const uint32_t bxr = (uint32_t)((ebase >> 1) & 3);
    const uint32_t bhalf = (uint32_t)((lane >> 3) & 1);

    float4 p00 = *(const float4*)(aP0), p01 = *(const float4*)(aP0 + 4);
    float4 p10 = *(const float4*)(aP1), p11 = *(const float4*)(aP1 + 4);
    uint4 wh = *(const uint4*)(whP), wl = *(const uint4*)(wlP);
    {
        uint4 h0, l0, h1, l1;
        split8(p00, p01, h0, l0);
        split8(p10, p11, h1, l1);
        *(uint4*)(smem + OFF_AHI + sA0) = h0;
        *(uint4*)(smem + OFF_ALO + sA0) = l0;
        *(uint4*)(smem + OFF_AHI + sA1) = h1;
        *(uint4*)(smem + OFF_ALO + sA1) = l1;
        *(uint4*)(smem + OFF_BHI + sB) = wh;
        *(uint4*)(smem + OFF_BLO + sB) = wl;
    }
    __syncthreads();

    for (int chunk = 0; chunk < NCHUNKS; chunk++) {
        const uint32_t cb = (uint32_t)((chunk & 1) * STAGE_BYTES);
        const uint32_t nb = (uint32_t)(((chunk + 1) & 1) * STAGE_BYTES);
        const bool more = (chunk + 1 < NCHUNKS);

        if (more) {
            const int kb = (chunk + 1) * KCHUNK;
            p00 = *(const float4*)(aP0 + kb); p01 = *(const float4*)(aP0 + kb + 4);
            p10 = *(const float4*)(aP1 + kb); p11 = *(const float4*)(aP1 + kb + 4);
            wh = *(const uint4*)(whP + kb);   wl = *(const uint4*)(wlP + kb);
        }

#pragma unroll
        for (int s = 0; s < 2; s++) {
            uint32_t ah[4], al[4];
            {
                const uint32_t ach = (uint32_t)(2 * s) + ahalf;
                const uint32_t ao = (uint32_t)(arow * 64) + ((ach ^ axr) << 4);
                LDSM_X4(ah[0], ah[1], ah[2], ah[3], sb + cb + OFF_AHI + ao);
                LDSM_X4(al[0], al[1], al[2], al[3], sb + cb + OFF_ALO + ao);
            }
            uint32_t bh[16], bl[16];
#pragma unroll
            for (int jt = 0; jt < 4; jt++) {
                const int erow = jt * 16 + ebase;
                const uint32_t bch = (uint32_t)(2 * s) + bhalf;
                const uint32_t bo = (uint32_t)(erow * 64) + ((bch ^ bxr) << 4);
                LDSM_X4(bh[4 * jt], bh[4 * jt + 1], bh[4 * jt + 2], bh[4 * jt + 3],
                        sb + cb + OFF_BHI + bo);
                LDSM_X4(bl[4 * jt], bl[4 * jt + 1], bl[4 * jt + 2], bl[4 * jt + 3],
                        sb + cb + OFF_BLO + bo);
            }
#pragma unroll
            for (int jt = 0; jt < 4; jt++) {
                mma_bf16(acc[2 * jt], ah, bh[4 * jt], bh[4 * jt + 1]);
                mma_bf16(acc[2 * jt + 1], ah, bh[4 * jt + 2], bh[4 * jt + 3]);
            }
#pragma unroll
            for (int jt = 0; jt < 4; jt++) {
                mma_bf16(acc[2 * jt], ah, bl[4 * jt], bl[4 * jt + 1]);
                mma_bf16(acc[2 * jt + 1], ah, bl[4 * jt + 2], bl[4 * jt + 3]);
            }
#pragma unroll
            for (int jt = 0; jt < 4; jt++) {
                mma_bf16(acc[2 * jt], al, bh[4 * jt], bh[4 * jt + 1]);
                mma_bf16(acc[2 * jt + 1], al, bh[4 * jt + 2], bh[4 * jt + 3]);
            }
        }

        if (more) {
            uint4 h0, l0, h1, l1;
            split8(p00, p01, h0, l0);
            split8(p10, p11, h1, l1);
            *(uint4*)(smem + nb + OFF_AHI + sA0) = h0;
            *(uint4*)(smem + nb + OFF_ALO + sA0) = l0;
            *(uint4*)(smem + nb + OFF_AHI + sA1) = h1;
            *(uint4*)(smem + nb + OFF_ALO + sA1) = l1;
            *(uint4*)(smem + nb + OFF_BHI + sB) = wh;
            *(uint4*)(smem + nb + OFF_BLO + sB) = wl;
        }
        __syncthreads();
    }

    {
        const int r0 = wid * 16 + (lane >> 2);
        const int cbo = 2 * (lane & 3);
#pragma unroll
        for (int j = 0; j < 8; j++) {
            const int col = j * 8 + cbo;
            *(float2*)(Cs + r0 * CPAD + col) = make_float2(acc[j][0], acc[j][1]);
            *(float2*)(Cs + (r0 + 8) * CPAD + col) = make_float2(acc[j][2], acc[j][3]);
        }
    }
    __syncthreads();

#pragma unroll 1
    for (int t16 = 0; t16 < 16; t16++) {
        const int tok = wid * 16 + t16;
        const float v0 = Cs[tok * CPAD + lane];
        const float v1 = Cs[tok * CPAD + lane + 32];
        const long gtok = tokenBase + tok;

        float* crow = C + gtok * E_DIM;
        crow[lane] = v0;
        crow[lane + 32] = v1;

        float m = fmaxf(v0, v1);
#pragma unroll
        for (int o = 16; o; o >>= 1) m = fmaxf(m, __shfl_xor_sync(0xffffffffu, m, o));

        float e0 = __expf(v0 - m);
        float e1 = __expf(v1 - m);
        float s = e0 + e1;
#pragma unroll
        for (int o = 16; o; o >>= 1) s += __shfl_xor_sync(0xffffffffu, s, o);
        float inv = 1.0f / s;

        float* prow = P + gtok * E_DIM;
        prow[lane] = e0 * inv;
        prow[lane + 32] = e1 * inv;

        float bv; int bi;
        if (v0 >= v1) { bv = v0; bi = lane; } else { bv = v1; bi = lane + 32; }
#pragma unroll
        for (int o = 16; o; o >>= 1) {
            float ov = __shfl_xor_sync(0xffffffffu, bv, o);
            int   oi = __shfl_xor_sync(0xffffffffu, bi, o);
            if (ov > bv || (ov == bv && oi < bi)) { bv = ov; bi = oi; }
        }
        float c0 = (lane == bi) ? -INFINITY : v0;
        float c1 = (lane + 32 == bi) ? -INFINITY : v1;
        float sv; int si;
        if (c0 >= c1) { sv = c0; si = lane; } else { sv = c1; si = lane + 32; }
#pragma unroll
        for (int o = 16; o; o >>= 1) {
            float ov = __shfl_xor_sync(0xffffffffu, sv, o);
            int   oi = __shfl_xor_sync(0xffffffffu, si, o);
            if (ov > sv || (ov == sv && oi < si)) { sv = ov; si = oi; }
        }
        float d0 = (lane == bi || lane == si) ? -INFINITY : v0;
        float d1 = (lane + 32 == bi || lane + 32 == si) ? -INFINITY : v1;
        float tv = fmaxf(d0, d1);
#pragma unroll
        for (int o = 16; o; o >>= 1) tv = fmaxf(tv, __shfl_xor_sync(0xffffffffu, tv, o));

        if (lane == 0) {
            IDX[gtok * 2 + 0] = (float)bi;
            IDX[gtok * 2 + 1] = (float)si;
            if ((bv - sv) < GAP_THRESH || (sv - tv) < GAP_THRESH) {
                int slot = atomicAdd(&g_flag_count, 1);
                if (slot < 32768) g_flag_tokens[slot] = (int)gtok;
            }
        }
    }
}

// ---------------------------------------------------------------------------
// Refine: two-tier fp64-free (validated R13/R14/R15 body). Tier-1 plain fp32
// 4-acc dot; tier-2 compensated fp32 only when affinity gaps < 1e-5.
// ---------------------------------------------------------------------------
__global__ __launch_bounds__(256) void refine_ties(const float* __restrict__ A,
                                                   const float* __restrict__ W,
                                                   float* __restrict__ IDX) {
    __shared__ float sA[H_DIM];
    __shared__ double dpart[E_DIM][4];
    __shared__ double dsum[2];
    __shared__ float fmx[2];
    __shared__ float af_s[E_DIM];
    __shared__ int s_need;

    int n = g_flag_count;
    if (n > 32768) n = 32768;

    const int t = threadIdx.x;
    const int e = t & 63;
    const int seg = t >> 6;

    for (int it = blockIdx.x; it < n; it += gridDim.x) {
        const int tok = g_flag_tokens[it];
        const float* arow = A + (long)tok * H_DIM;
        for (int k = t * 4; k < H_DIM; k += 1024)
            *(float4*)(sA + k) = *(const float4*)(arow + k);
        __syncthreads();

        const float* wrow = W + (long)e * H_DIM + seg * 1024;
        const float* aseg = sA + seg * 1024;

        {
            float a0 = 0, a1 = 0, a2 = 0, a3 = 0;
#pragma unroll 4
            for (int k = 0; k < 1024; k += 4) {
                float4 w4 = *(const float4*)(wrow + k);
                float4 a4 = *(const float4*)(aseg + k);
                a0 = __fmaf_rn(a4.x, w4.x, a0);
                a1 = __fmaf_rn(a4.y, w4.y, a1);
                a2 = __fmaf_rn(a4.z, w4.z, a2);
                a3 = __fmaf_rn(a4.w, w4.w, a3);
            }
            dpart[e][seg] = ((double)a0 + (double)a1) + ((double)a2 + (double)a3);
        }
        __syncthreads();

        for (int tier = 0; tier < 2; tier++) {
            double dl = 0.0, ex = 0.0;
            if (t < 64) {
                dl = (dpart[e][0] + dpart[e][1]) + (dpart[e][2] + dpart[e][3]);
                float mv = (float)dl;
#pragma unroll
                for (int o = 16; o; o >>= 1)
                    mv = fmaxf(mv, __shfl_xor_sync(0xffffffffu, mv, o));
                if ((t & 31) == 0) fmx[t >> 5] = mv;
            }
            __syncthreads();
            if (t < 64) {
                const float m = fmaxf(fmx[0], fmx[1]);
                ex = exp(dl - (double)m);
                double sm = ex;
#pragma unroll
                for (int o = 16; o; o >>= 1)
                    sm += __shfl_xor_sync(0xffffffffu, sm, o);
                if ((t & 31) == 0) dsum[t >> 5] = sm;
            }
            __syncthreads();
            if (t < 64) af_s[e] = (float)(ex / (dsum[0] + dsum[1]));
            __syncthreads();

            if (t == 0) {
                int bi = 0;
#pragma unroll
                for (int i = 1; i < E_DIM; i++)
                    if (af_s[i] > af_s[bi]) bi = i;
                int si = (bi == 0) ? 1 : 0;
#pragma unroll
                for (int i = 0; i < E_DIM; i++) {
                    if (i == bi || i == si) continue;
                    if (af_s[i] > af_s[si]) si = i;
                }
                float ti = -INFINITY;
#pragma unroll
                for (int i = 0; i < E_DIM; i++) {
                    if (i == bi || i == si) continue;
                    ti = fmaxf(ti, af_s[i]);
                }
                const int ambiguous = (tier == 0) &&
                    ((af_s[bi] - af_s[si] < 1e-5f) || (af_s[si] - ti < 1e-5f));
                s_need = ambiguous;
                if (!ambiguous) {
                    IDX[(long)tok * 2 + 0] = (float)bi;
                    IDX[(long)tok * 2 + 1] = (float)si;
                }
            }
            __syncthreads();
            if (!s_need) break;

            {
                float s = 0.0f, c = 0.0f, ce = 0.0f;
#pragma unroll 4
                for (int k = 0; k < 1024; k += 4) {
                    float4 w4 = *(const float4*)(wrow + k);
                    float4 a4 = *(const float4*)(aseg + k);
#define ACC1(av, wv) {                                   \
                    float p = __fmul_rn((av), (wv));     \
                    ce += __fmaf_rn((av), (wv), -p);     \
                    float t2 = __fadd_rn(s, p);          \
                    float z = t2 - s;                    \
                    c += (s - (t2 - z)) + (p - z);       \
                    s = t2; }
                    ACC1(a4.x, w4.x); ACC1(a4.y, w4.y);
                    ACC1(a4.z, w4.z); ACC1(a4.w, w4.w);
#undef ACC1
                }
                dpart[e][seg] = (double)s + ((double)c + (double)ce);
            }
            __syncthreads();
        }
        __syncthreads();
    }
}

// ---------------------------------------------------------------------------
// d_out: [logits T*64 | affinities T*64 | indices-as-float T*2], fp32.
// ---------------------------------------------------------------------------
extern "C" void kernel_launch(void* const* d_in, const int* in_sizes, int n_in,
                              void* d_out, int out_size) {
    const float* A = (const float*)d_in[0];
    const float* W = (const float*)d_in[1];
    const int T = in_sizes[0] / H_DIM;  // 32768

    float* out = (float*)d_out;
    float* logits = out;
    float* affin  = out + (long)T * E_DIM;
    float* idx    = out + 2L * T * E_DIM;

    w_split<<<256, 256>>>(W);
    router_gemm_mma<<<T / TILE_M, 256>>>(A, logits, affin, idx);
    refine_ties<<<256, 256>>>(A, W, idx);
}